// round 11
// baseline (speedup 1.0000x reference)
#include <cuda_runtime.h>

typedef unsigned long long ull;

// ---- packed f32x2 helpers (Blackwell sm_100+) ----
__device__ __forceinline__ ull pk2(float x, float y) {
    ull r; asm("mov.b64 %0, {%1, %2};" : "=l"(r) : "f"(x), "f"(y)); return r;
}
__device__ __forceinline__ ull dup2(float x) {
    ull r; asm("mov.b64 %0, {%1, %1};" : "=l"(r) : "f"(x)); return r;
}
__device__ __forceinline__ void fma2(ull& d, ull a, ull b) {
    asm("fma.rn.f32x2 %0, %1, %2, %0;" : "+l"(d) : "l"(a), "l"(b));
}
__device__ __forceinline__ float2 upk2(ull v) {
    float2 r; asm("mov.b64 {%0, %1}, %2;" : "=f"(r.x), "=f"(r.y) : "l"(v)); return r;
}
__device__ __forceinline__ ull add2(ull a, ull b) {
    ull r; asm("add.rn.f32x2 %0, %1, %2;" : "=l"(r) : "l"(a), "l"(b)); return r;
}

// Algebra:
//   layer-1 preact z1[j] = TAB[da*10+db][j] + p0 * d1[j]
//     TAB[idx][j] = Ea[da]·W1[j,0:8] + Eb[db]·W1[j,8:16] + b1[j] + W1[j,17]
//     d1[j]       = W1[j,16] - W1[j,17]
//   carry = softmax(c) = (p0, 1-p0) with p0 = sigmoid(c0 - c1)
//
// Parallelization: 4 lanes per batch row. Lane quarter q owns h2 outputs
// [8q, 8q+8) as 4 packed f32x2 accumulators; head partials per lane; 2-round
// butterfly (xor 1, xor 2) combines the 12 outputs. ~80 live regs -> 5 CTAs/SM.

__global__ __launch_bounds__(128, 5)
void mlp_seq_kernel(const int* __restrict__ A, const int* __restrict__ Bd,
                    const float* __restrict__ Ea, const float* __restrict__ Eb,
                    const float* __restrict__ W1, const float* __restrict__ b1,
                    const float* __restrict__ W2, const float* __restrict__ b2,
                    const float* __restrict__ Wd, const float* __restrict__ bd,
                    const float* __restrict__ Wc, const float* __restrict__ bc,
                    float* __restrict__ out, int Bn)
{
    __shared__ float2 sT2[32][100];                // sT2[j2][idx] = (TAB[idx][2j2], TAB[idx][2j2+1])
    __shared__ float2 sD1p[32];                    // (d1[2j2], d1[2j2+1])
    __shared__ __align__(16) ull sW2q[64][4][4];   // [j][q][m] = (W2[8q+2m][j], W2[8q+2m+1][j])
    __shared__ __align__(16) ull sB2q[4][4];
    __shared__ __align__(16) ull sWop[32][6];      // [i][k2] = (Wo[2k2][i], Wo[2k2+1][i]), Wo=[Wd;Wc]
    __shared__ ull sBop[6];

    const int tid = threadIdx.x;

    // ---------------- per-block precompute (amortized over 32 rows x 64 steps) ----------------
    for (int t = tid; t < 32; t += 128) {
        int j0 = 2 * t;
        sD1p[t] = make_float2(W1[j0 * 18 + 16] - W1[j0 * 18 + 17],
                              W1[(j0 + 1) * 18 + 16] - W1[(j0 + 1) * 18 + 17]);
    }

    for (int t = tid; t < 64 * 16; t += 128) {
        int j = t >> 4, q = (t >> 2) & 3, m = t & 3;
        int r0 = 8 * q + 2 * m;
        sW2q[j][q][m] = pk2(W2[r0 * 64 + j], W2[(r0 + 1) * 64 + j]);
    }
    if (tid < 16) {
        int q = tid >> 2, m = tid & 3;
        int r0 = 8 * q + 2 * m;
        sB2q[q][m] = pk2(b2[r0], b2[r0 + 1]);
    }

    for (int t = tid; t < 32 * 6; t += 128) {
        int i = t / 6, k2 = t % 6;
        int k0 = 2 * k2, k1 = 2 * k2 + 1;
        float w0 = (k0 < 10) ? Wd[k0 * 32 + i] : Wc[(k0 - 10) * 32 + i];
        float w1 = (k1 < 10) ? Wd[k1 * 32 + i] : Wc[(k1 - 10) * 32 + i];
        sWop[i][k2] = pk2(w0, w1);
    }
    if (tid < 6) {
        int k0 = 2 * tid, k1 = k0 + 1;
        float v0 = (k0 < 10) ? bd[k0] : bc[k0 - 10];
        float v1 = (k1 < 10) ? bd[k1] : bc[k1 - 10];
        sBop[tid] = pk2(v0, v1);
    }

    for (int t = tid; t < 64 * 100; t += 128) {
        int j = t / 100, idx = t - j * 100;
        int da = idx / 10, db = idx - da * 10;
        const float* w = W1 + j * 18;
        float s = b1[j] + w[17];
#pragma unroll
        for (int k = 0; k < 8; k++) s = fmaf(Ea[da * 8 + k], w[k], s);
#pragma unroll
        for (int k = 0; k < 8; k++) s = fmaf(Eb[db * 8 + k], w[8 + k], s);
        // write scalar half of the float2 entry
        ((float*)&sT2[j >> 1][idx])[j & 1] = s;
    }
    __syncthreads();

    // ---------------- main recurrence: 4 lanes = 1 batch row ----------------
    int bi = (blockIdx.x * 128 + tid) >> 2;
    const int q = tid & 3;
    if (bi >= Bn) bi = Bn - 1;                 // duplicate tail, same values written

    const long long rowoff = (long long)bi * 64;
    const int* ap  = A  + rowoff;
    const int* bpp = Bd + rowoff;
    float2* oD = (float2*)out + rowoff * 5;                       // digit logits [B,L,10]
    float2* oC = (float2*)(out + (long long)Bn * 640) + rowoff;   // carry logits [B,L,2]

    const ull bq0 = sB2q[q][0], bq1 = sB2q[q][1], bq2 = sB2q[q][2], bq3 = sB2q[q][3];
    const int ibase = 8 * q;

    float p0 = 1.0f;                 // carry0 = (1, 0)
    int da = ap[0], db = bpp[0];

#pragma unroll 1
    for (int l = 0; l < 64; l++) {
        const int idx = da * 10 + db;
        const int nl = (l < 63) ? (l + 1) : 63;   // prefetch next digits
        da = ap[nl]; db = bpp[nl];

        const ull p0p = dup2(p0);

        // ---- fused layer-1 + this lane's quarter of the W2 GEMV ----
        ull acc0 = bq0, acc1 = bq1, acc2 = bq2, acc3 = bq3;

#pragma unroll 2
        for (int j2 = 0; j2 < 32; j2++) {
            float2 tb = sT2[j2][idx];
            float2 dd = sD1p[j2];
            ull z = pk2(tb.x, tb.y);
            fma2(z, p0p, pk2(dd.x, dd.y));        // z = tab + p0*d1 (packed pair)
            float2 zf = upk2(z);
            float h0 = fmaxf(zf.x, 0.0f);
            float h1 = fmaxf(zf.y, 0.0f);

            {
                ull x = dup2(h0);
                const ulonglong2* wr = (const ulonglong2*)&sW2q[2 * j2][q][0];
                ulonglong2 w0 = wr[0], w1 = wr[1];
                fma2(acc0, w0.x, x); fma2(acc1, w0.y, x);
                fma2(acc2, w1.x, x); fma2(acc3, w1.y, x);
            }
            {
                ull x = dup2(h1);
                const ulonglong2* wr = (const ulonglong2*)&sW2q[2 * j2 + 1][q][0];
                ulonglong2 w0 = wr[0], w1 = wr[1];
                fma2(acc0, w0.x, x); fma2(acc1, w0.y, x);
                fma2(acc2, w1.x, x); fma2(acc3, w1.y, x);
            }
        }

        // ---- head partials over this lane's 8 h2 values ----
        ull o0, o1, o2, o3, o4, o5;
        if (q == 0) { o0 = sBop[0]; o1 = sBop[1]; o2 = sBop[2];
                      o3 = sBop[3]; o4 = sBop[4]; o5 = sBop[5]; }
        else        { o0 = o1 = o2 = o3 = o4 = o5 = 0ull; }

        ull accs[4] = {acc0, acc1, acc2, acc3};
#pragma unroll
        for (int m = 0; m < 4; m++) {
            float2 hv = upk2(accs[m]);
            float ha = fmaxf(hv.x, 0.0f);
            float hb = fmaxf(hv.y, 0.0f);
            ull xa = dup2(ha), xb = dup2(hb);
            const ulonglong2* wa = (const ulonglong2*)sWop[ibase + 2 * m];
            const ulonglong2* wb = (const ulonglong2*)sWop[ibase + 2 * m + 1];
            ulonglong2 wa0 = wa[0], wa1 = wa[1], wa2 = wa[2];
            fma2(o0, wa0.x, xa); fma2(o1, wa0.y, xa);
            fma2(o2, wa1.x, xa); fma2(o3, wa1.y, xa);
            fma2(o4, wa2.x, xa); fma2(o5, wa2.y, xa);
            ulonglong2 wb0 = wb[0], wb1 = wb[1], wb2 = wb[2];
            fma2(o0, wb0.x, xb); fma2(o1, wb0.y, xb);
            fma2(o2, wb1.x, xb); fma2(o3, wb1.y, xb);
            fma2(o4, wb2.x, xb); fma2(o5, wb2.y, xb);
        }

        // ---- 4-lane butterfly reduction (packed adds, 64-bit shfl) ----
        o0 = add2(o0, __shfl_xor_sync(0xFFFFFFFFu, o0, 1));
        o1 = add2(o1, __shfl_xor_sync(0xFFFFFFFFu, o1, 1));
        o2 = add2(o2, __shfl_xor_sync(0xFFFFFFFFu, o2, 1));
        o3 = add2(o3, __shfl_xor_sync(0xFFFFFFFFu, o3, 1));
        o4 = add2(o4, __shfl_xor_sync(0xFFFFFFFFu, o4, 1));
        o5 = add2(o5, __shfl_xor_sync(0xFFFFFFFFu, o5, 1));
        o0 = add2(o0, __shfl_xor_sync(0xFFFFFFFFu, o0, 2));
        o1 = add2(o1, __shfl_xor_sync(0xFFFFFFFFu, o1, 2));
        o2 = add2(o2, __shfl_xor_sync(0xFFFFFFFFu, o2, 2));
        o3 = add2(o3, __shfl_xor_sync(0xFFFFFFFFu, o3, 2));
        o4 = add2(o4, __shfl_xor_sync(0xFFFFFFFFu, o4, 2));
        o5 = add2(o5, __shfl_xor_sync(0xFFFFFFFFu, o5, 2));

        float2 cv = upk2(o5);

        // split stores across the 4 lanes
        float2* od = oD + (long long)l * 5;
        if (q == 0)      { od[0] = upk2(o0); od[1] = upk2(o1); }
        else if (q == 1) { od[2] = upk2(o2); od[3] = upk2(o3); }
        else if (q == 2) { od[4] = upk2(o4); }
        else             { oC[l] = cv; }

        // next carry prob: softmax(c)[0] = sigmoid(c0 - c1); identical in all 4 lanes
        p0 = 1.0f / (1.0f + expf(cv.y - cv.x));
    }
}

extern "C" void kernel_launch(void* const* d_in, const int* in_sizes, int n_in,
                              void* d_out, int out_size)
{
    const int*   A  = (const int*)  d_in[0];
    const int*   Bd = (const int*)  d_in[1];
    const float* Ea = (const float*)d_in[2];
    const float* Eb = (const float*)d_in[3];
    const float* W1 = (const float*)d_in[4];
    const float* b1 = (const float*)d_in[5];
    const float* W2 = (const float*)d_in[6];
    const float* b2 = (const float*)d_in[7];
    const float* Wd = (const float*)d_in[8];
    const float* bd = (const float*)d_in[9];
    const float* Wc = (const float*)d_in[10];
    const float* bc = (const float*)d_in[11];

    int Bn = in_sizes[0] / 64;
    int grid = (Bn + 31) / 32;      // 32 rows per block (128 threads, 4 per row)
    mlp_seq_kernel<<<grid, 128>>>(A, Bd, Ea, Eb, W1, b1, W2, b2, Wd, bd, Wc, bc,
                                  (float*)d_out, Bn);
}

// round 14
// speedup vs baseline: 2.5253x; 2.5253x over previous
#include <cuda_runtime.h>
#include <math.h>

typedef unsigned long long ull;

#define NIDX 100
#define NSEG 65      // segments 0..64 (<=64 knees)
#define MAXB 65536

// ---- persistent scratch (module statics; the sanctioned scratch path) ----
__device__ __align__(16) float gKnees[NIDX * NSEG];        // sorted knees, padded with 2.0f
__device__ __align__(16) float gAB[NIDX * NSEG * 64];      // [idx][seg][0..31]=A, [32..63]=B
__device__ unsigned char gIdxT[64 * MAXB];                 // [l][b] packed digit-pair index

// ---- packed f32x2 helpers ----
__device__ __forceinline__ ull pk2(float x, float y) {
    ull r; asm("mov.b64 %0, {%1, %2};" : "=l"(r) : "f"(x), "f"(y)); return r;
}
__device__ __forceinline__ ull dup2(float x) {
    ull r; asm("mov.b64 %0, {%1, %1};" : "=l"(r) : "f"(x)); return r;
}
__device__ __forceinline__ void fma2(ull& d, ull a, ull b) {
    asm("fma.rn.f32x2 %0, %1, %2, %0;" : "+l"(d) : "l"(a), "l"(b));
}
__device__ __forceinline__ float2 upk2(ull v) {
    float2 r; asm("mov.b64 {%0, %1}, %2;" : "=f"(r.x), "=f"(r.y) : "l"(v)); return r;
}

// ================= kernel T: pack digits, transpose to [l][b] u8 =================
__global__ void digits_kernel(const int* __restrict__ A, const int* __restrict__ Bd, int Bn)
{
    __shared__ unsigned char tile[64][65];
    int b0 = blockIdx.x * 64;
    for (int t = threadIdx.x; t < 64 * 64; t += 256) {
        int bl = t >> 6, l = t & 63;
        int bi = b0 + bl;
        if (bi < Bn) {
            int av = A[bi * 64 + l], bv = Bd[bi * 64 + l];
            tile[l][bl] = (unsigned char)(av * 10 + bv);
        }
    }
    __syncthreads();
    for (int t = threadIdx.x; t < 64 * 64; t += 256) {
        int l = t >> 6, bl = t & 63;
        if (b0 + bl < Bn)
            gIdxT[l * Bn + b0 + bl] = tile[l][bl];
    }
}

// ================= kernel P: build knees + per-segment (A,B) tables =================
// z1[j](p0) = t_j + p0*d_j ; t_j = b1[j]+W1[j,17]+Ea[da]·W1[j,0:8]+Eb[db]·W1[j,8:16],
// d_j = W1[j,16]-W1[j,17].  h2_pre[i](p0) = b2[i] + sum_j W2[i,j]*relu(z1[j]) is
// piecewise-linear in p0: within a segment, h2_pre[i] = A[i] + p0*B[i].
__global__ void precomp_kernel(const float* __restrict__ Ea, const float* __restrict__ Eb,
                               const float* __restrict__ W1, const float* __restrict__ b1,
                               const float* __restrict__ W2, const float* __restrict__ b2)
{
    __shared__ float st[64], sd[64], skey[64], sortedK[64];
    __shared__ int   sortedJ[64];

    const int idx = blockIdx.x;          // 0..99
    const int j   = threadIdx.x;         // 0..63
    const int da = idx / 10, db = idx - 10 * (idx / 10);

    const float* w = W1 + j * 18;
    float t = b1[j] + w[17];
#pragma unroll
    for (int k = 0; k < 8; k++) t = fmaf(Ea[da * 8 + k], w[k], t);
#pragma unroll
    for (int k = 0; k < 8; k++) t = fmaf(Eb[db * 8 + k], w[8 + k], t);
    float d = w[16] - w[17];
    st[j] = t; sd[j] = d;

    float knee = 2.0f;                   // invalid marker (sorts last)
    if (d != 0.0f) {
        float kn = -t / d;
        if (kn > 0.0f && kn < 1.0f) knee = kn;
    }
    skey[j] = knee;
    __syncthreads();

    // rank sort (stable)
    int rank = 0;
    for (int m = 0; m < 64; m++) {
        float km = skey[m];
        rank += (km < knee) || (km == knee && m < j);
    }
    sortedK[rank] = knee; sortedJ[rank] = j;
    __syncthreads();

    gKnees[idx * NSEG + j] = sortedK[j];
    if (j == 0) gKnees[idx * NSEG + 64] = 2.0f;

    // segment walk: threads 0..31 each own one h2 output i
    if (j < 32) {
        const int i = j;
        float Av = b2[i], Bv = 0.0f;
#pragma unroll 1
        for (int m = 0; m < 64; m++) {
            float tm = st[m], dm = sd[m];
            bool act = (tm > 0.0f) || (tm == 0.0f && dm > 0.0f);   // state at p0->0+
            if (act) {
                float wv = W2[i * 64 + m];
                Av = fmaf(wv, tm, Av);
                Bv = fmaf(wv, dm, Bv);
            }
        }
        float* base = gAB + idx * NSEG * 64;
        base[i] = Av; base[32 + i] = Bv;
#pragma unroll 1
        for (int s = 1; s <= 64; s++) {
            float key = sortedK[s - 1];
            if (key < 1.0f) {            // real crossing inside (0,1)
                int jj = sortedJ[s - 1];
                float sgn = (sd[jj] > 0.0f) ? 1.0f : -1.0f;   // d>0: turns on, d<0: turns off
                float wv = W2[i * 64 + jj];
                Av = fmaf(sgn * wv, st[jj], Av);
                Bv = fmaf(sgn * wv, sd[jj], Bv);
            }
            base[s * 64 + i] = Av; base[s * 64 + 32 + i] = Bv;
        }
    }
}

// ================= kernel M: main recurrence, 1 thread = 1 row =================
__global__ __launch_bounds__(128, 5)
void mlp_seq_kernel(const float* __restrict__ Wd, const float* __restrict__ bd,
                    const float* __restrict__ Wc, const float* __restrict__ bc,
                    float* __restrict__ out, int Bn)
{
    __shared__ float sKnees[NIDX * NSEG];                 // 26 KB
    __shared__ __align__(16) ull sWop[32][6];             // [i][k2]=(Wo[2k2][i],Wo[2k2+1][i])
    __shared__ ull sBop[6];

    const int tid = threadIdx.x;
    for (int t = tid; t < NIDX * NSEG; t += 128)
        sKnees[t] = gKnees[t];
    for (int t = tid; t < 32 * 6; t += 128) {
        int i = t / 6, k2 = t % 6;
        int k0 = 2 * k2, k1 = k0 + 1;
        float w0 = (k0 < 10) ? Wd[k0 * 32 + i] : Wc[(k0 - 10) * 32 + i];
        float w1 = (k1 < 10) ? Wd[k1 * 32 + i] : Wc[(k1 - 10) * 32 + i];
        sWop[i][k2] = pk2(w0, w1);
    }
    if (tid < 6) {
        int k0 = 2 * tid, k1 = k0 + 1;
        float v0 = (k0 < 10) ? bd[k0] : bc[k0 - 10];
        float v1 = (k1 < 10) ? bd[k1] : bc[k1 - 10];
        sBop[tid] = pk2(v0, v1);
    }
    __syncthreads();

    const int bi = blockIdx.x * 128 + tid;
    if (bi >= Bn) return;

    float* oDigit = out + (ull)bi * 640;                  // [B][64][10]
    float* oCarry = out + (ull)Bn * 640 + (ull)bi * 128;  // [B][64][2]

    ull ob0 = sBop[0], ob1 = sBop[1], ob2 = sBop[2],
        ob3 = sBop[3], ob4 = sBop[4], ob5 = sBop[5];

    float p0 = 1.0f;                                      // carry0 = (1,0)

#pragma unroll 1
    for (int l = 0; l < 64; l++) {
        const int idx = (int)gIdxT[l * Bn + bi];          // coalesced u8

        // binary search: seg = #knees < p0 (64 sorted entries, 2.0f padding)
        const float* kn = sKnees + idx * NSEG;
        int lo = 0;
#pragma unroll
        for (int bstep = 32; bstep >= 1; bstep >>= 1)
            lo += (kn[lo + bstep - 1] < p0) ? bstep : 0;

        // h2_pre = A + p0*B  (256B contiguous, L2-hot)
        const ulonglong2* abp = (const ulonglong2*)(gAB + (idx * NSEG + lo) * 64);
        const ull p0p = dup2(p0);
        float h[32];
#pragma unroll
        for (int q = 0; q < 8; q++) {
            ulonglong2 av = abp[q];        // A pairs
            ulonglong2 bv = abp[8 + q];    // B pairs
            ull z0 = av.x; fma2(z0, bv.x, p0p);
            ull z1 = av.y; fma2(z1, bv.y, p0p);
            float2 f0 = upk2(z0), f1 = upk2(z1);
            h[4 * q + 0] = fmaxf(f0.x, 0.0f);
            h[4 * q + 1] = fmaxf(f0.y, 0.0f);
            h[4 * q + 2] = fmaxf(f1.x, 0.0f);
            h[4 * q + 3] = fmaxf(f1.y, 0.0f);
        }

        // 12-wide head
        ull o0 = ob0, o1 = ob1, o2 = ob2, o3 = ob3, o4 = ob4, o5 = ob5;
#pragma unroll
        for (int i = 0; i < 32; i++) {
            ull x = dup2(h[i]);
            const ulonglong2* wv = (const ulonglong2*)sWop[i];   // broadcast LDS
            ulonglong2 w0 = wv[0], w1 = wv[1], w2v = wv[2];
            fma2(o0, w0.x, x);  fma2(o1, w0.y, x);
            fma2(o2, w1.x, x);  fma2(o3, w1.y, x);
            fma2(o4, w2v.x, x); fma2(o5, w2v.y, x);
        }

        float2* od = (float2*)(oDigit + l * 10);          // 8B-aligned
        od[0] = upk2(o0); od[1] = upk2(o1); od[2] = upk2(o2);
        od[3] = upk2(o3); od[4] = upk2(o4);
        float2 cv = upk2(o5);
        *(float2*)(oCarry + l * 2) = cv;

        // next carry prob: softmax(c)[0] = sigmoid(c0 - c1)
        p0 = 1.0f / (1.0f + expf(cv.y - cv.x));
    }
}

extern "C" void kernel_launch(void* const* d_in, const int* in_sizes, int n_in,
                              void* d_out, int out_size)
{
    const int*   A  = (const int*)  d_in[0];
    const int*   Bd = (const int*)  d_in[1];
    const float* Ea = (const float*)d_in[2];
    const float* Eb = (const float*)d_in[3];
    const float* W1 = (const float*)d_in[4];
    const float* b1 = (const float*)d_in[5];
    const float* W2 = (const float*)d_in[6];
    const float* b2 = (const float*)d_in[7];
    const float* Wd = (const float*)d_in[8];
    const float* bd = (const float*)d_in[9];
    const float* Wc = (const float*)d_in[10];
    const float* bc = (const float*)d_in[11];

    int Bn = in_sizes[0] / 64;
    if (Bn > MAXB) Bn = MAXB;

    digits_kernel<<<(Bn + 63) / 64, 256>>>(A, Bd, Bn);
    precomp_kernel<<<NIDX, 64>>>(Ea, Eb, W1, b1, W2, b2);
    mlp_seq_kernel<<<(Bn + 127) / 128, 128>>>(Wd, bd, Wc, bc, (float*)d_out, Bn);
}

// round 15
// speedup vs baseline: 4.4732x; 1.7713x over previous
#include <cuda_runtime.h>
#include <math.h>

typedef unsigned long long ull;

#define NIDX 100
#define NSEG 65      // segments 0..64 (<=64 knees)
#define MAXB 65536

// ---- persistent scratch (module statics; the sanctioned scratch path) ----
__device__ __align__(16) float gKnees[NIDX * NSEG];        // sorted knees, padded with 2.0f
__device__ __align__(16) float gAB[NIDX * NSEG * 64];      // [idx][seg][0..31]=A, [32..63]=B
__device__ unsigned char gIdxT[64 * MAXB];                 // [l][b] packed digit-pair index

// ---- packed f32x2 helpers ----
__device__ __forceinline__ ull pk2(float x, float y) {
    ull r; asm("mov.b64 %0, {%1, %2};" : "=l"(r) : "f"(x), "f"(y)); return r;
}
__device__ __forceinline__ ull dup2(float x) {
    ull r; asm("mov.b64 %0, {%1, %1};" : "=l"(r) : "f"(x)); return r;
}
__device__ __forceinline__ void fma2(ull& d, ull a, ull b) {
    asm("fma.rn.f32x2 %0, %1, %2, %0;" : "+l"(d) : "l"(a), "l"(b));
}
__device__ __forceinline__ float2 upk2(ull v) {
    float2 r; asm("mov.b64 {%0, %1}, %2;" : "=f"(r.x), "=f"(r.y) : "l"(v)); return r;
}
__device__ __forceinline__ ull add2(ull a, ull b) {
    ull r; asm("add.rn.f32x2 %0, %1, %2;" : "=l"(r) : "l"(a), "l"(b)); return r;
}

// ================= kernel T: pack digits, transpose to [l][b] u8 =================
__global__ void digits_kernel(const int* __restrict__ A, const int* __restrict__ Bd, int Bn)
{
    __shared__ unsigned char tile[64][65];
    int b0 = blockIdx.x * 64;
    for (int t = threadIdx.x; t < 64 * 64; t += 256) {
        int bl = t >> 6, l = t & 63;
        int bi = b0 + bl;
        if (bi < Bn) {
            int av = A[bi * 64 + l], bv = Bd[bi * 64 + l];
            tile[l][bl] = (unsigned char)(av * 10 + bv);
        }
    }
    __syncthreads();
    for (int t = threadIdx.x; t < 64 * 64; t += 256) {
        int l = t >> 6, bl = t & 63;
        if (b0 + bl < Bn)
            gIdxT[l * Bn + b0 + bl] = tile[l][bl];
    }
}

// ================= kernel P: build knees + per-segment (A,B) tables =================
__global__ void precomp_kernel(const float* __restrict__ Ea, const float* __restrict__ Eb,
                               const float* __restrict__ W1, const float* __restrict__ b1,
                               const float* __restrict__ W2, const float* __restrict__ b2)
{
    __shared__ float st[64], sd[64], skey[64], sortedK[64];
    __shared__ int   sortedJ[64];

    const int idx = blockIdx.x;          // 0..99
    const int j   = threadIdx.x;         // 0..63
    const int da = idx / 10, db = idx - 10 * (idx / 10);

    const float* w = W1 + j * 18;
    float t = b1[j] + w[17];
#pragma unroll
    for (int k = 0; k < 8; k++) t = fmaf(Ea[da * 8 + k], w[k], t);
#pragma unroll
    for (int k = 0; k < 8; k++) t = fmaf(Eb[db * 8 + k], w[8 + k], t);
    float d = w[16] - w[17];
    st[j] = t; sd[j] = d;

    float knee = 2.0f;
    if (d != 0.0f) {
        float kn = -t / d;
        if (kn > 0.0f && kn < 1.0f) knee = kn;
    }
    skey[j] = knee;
    __syncthreads();

    int rank = 0;
    for (int m = 0; m < 64; m++) {
        float km = skey[m];
        rank += (km < knee) || (km == knee && m < j);
    }
    sortedK[rank] = knee; sortedJ[rank] = j;
    __syncthreads();

    gKnees[idx * NSEG + j] = sortedK[j];
    if (j == 0) gKnees[idx * NSEG + 64] = 2.0f;

    if (j < 32) {
        const int i = j;
        float Av = b2[i], Bv = 0.0f;
#pragma unroll 1
        for (int m = 0; m < 64; m++) {
            float tm = st[m], dm = sd[m];
            bool act = (tm > 0.0f) || (tm == 0.0f && dm > 0.0f);
            if (act) {
                float wv = W2[i * 64 + m];
                Av = fmaf(wv, tm, Av);
                Bv = fmaf(wv, dm, Bv);
            }
        }
        float* base = gAB + idx * NSEG * 64;
        base[i] = Av; base[32 + i] = Bv;
#pragma unroll 1
        for (int s = 1; s <= 64; s++) {
            float key = sortedK[s - 1];
            if (key < 1.0f) {
                int jj = sortedJ[s - 1];
                float sgn = (sd[jj] > 0.0f) ? 1.0f : -1.0f;
                float wv = W2[i * 64 + jj];
                Av = fmaf(sgn * wv, st[jj], Av);
                Bv = fmaf(sgn * wv, sd[jj], Bv);
            }
            base[s * 64 + i] = Av; base[s * 64 + 32 + i] = Bv;
        }
    }
}

// ================= kernel M: main recurrence, 8 lanes = 1 row =================
// Lane r of an 8-lane group owns h2 outputs [4r, 4r+4): cooperative coalesced
// AB fetch (1 line per row per instruction), register-resident head weights,
// 3-round butterfly for the 12 outputs. All lanes track identical p0.
__global__ __launch_bounds__(128, 4)
void mlp_seq_kernel(const float* __restrict__ Wd, const float* __restrict__ bd,
                    const float* __restrict__ Wc, const float* __restrict__ bc,
                    float* __restrict__ out, int Bn)
{
    __shared__ float sKnees[NIDX * NSEG];                 // 26 KB

    const int tid = threadIdx.x;
    for (int t = tid; t < NIDX * NSEG; t += 128)
        sKnees[t] = gKnees[t];
    __syncthreads();

    const int r  = tid & 7;                               // lane-in-row
    int bi = blockIdx.x * 16 + (tid >> 3);                // 16 rows per block
    if (bi >= Bn) bi = Bn - 1;                            // duplicate tail row

    // ---- register-resident head weights for this lane's 4 h-indices ----
    // wq[m][k2] = (Wo[2k2][4r+m], Wo[2k2+1][4r+m]), Wo = [Wd;Wc]
    ull wq[4][6];
#pragma unroll
    for (int m = 0; m < 4; m++) {
        int i = 4 * r + m;
#pragma unroll
        for (int k2 = 0; k2 < 6; k2++) {
            int k0 = 2 * k2, k1 = k0 + 1;
            float w0 = (k0 < 10) ? Wd[k0 * 32 + i] : Wc[(k0 - 10) * 32 + i];
            float w1 = (k1 < 10) ? Wd[k1 * 32 + i] : Wc[(k1 - 10) * 32 + i];
            wq[m][k2] = pk2(w0, w1);
        }
    }
    // bias counted once per row (lane 0 only)
    ull bo0 = 0, bo1 = 0, bo2 = 0, bo3 = 0, bo4 = 0, bo5 = 0;
    if (r == 0) {
        bo0 = pk2(bd[0], bd[1]); bo1 = pk2(bd[2], bd[3]); bo2 = pk2(bd[4], bd[5]);
        bo3 = pk2(bd[6], bd[7]); bo4 = pk2(bd[8], bd[9]); bo5 = pk2(bc[0], bc[1]);
    }

    float* oDigit = out + (ull)bi * 640;                  // [B][64][10]
    float* oCarry = out + (ull)Bn * 640 + (ull)bi * 128;  // [B][64][2]

    float p0 = 1.0f;                                      // carry0 = (1,0)

#pragma unroll 1
    for (int l = 0; l < 64; l++) {
        const int idx = (int)gIdxT[l * Bn + bi];          // 1 line per 4-row warp

        // binary search: seg = #knees < p0 (identical across the 8 lanes)
        const float* kn = sKnees + idx * NSEG;
        int lo = 0;
#pragma unroll
        for (int bstep = 32; bstep >= 1; bstep >>= 1)
            lo += (kn[lo + bstep - 1] < p0) ? bstep : 0;

        // cooperative AB fetch: lane r reads A[4r..4r+4), B[4r..4r+4)
        const float* base = gAB + (idx * NSEG + lo) * 64;
        float4 av = *(const float4*)(base + 4 * r);
        float4 bv = *(const float4*)(base + 32 + 4 * r);

        const ull p0p = dup2(p0);
        ull z0 = pk2(av.x, av.y); fma2(z0, pk2(bv.x, bv.y), p0p);
        ull z1 = pk2(av.z, av.w); fma2(z1, pk2(bv.z, bv.w), p0p);
        float2 f0 = upk2(z0), f1 = upk2(z1);
        float h0 = fmaxf(f0.x, 0.0f), h1 = fmaxf(f0.y, 0.0f);
        float h2 = fmaxf(f1.x, 0.0f), h3 = fmaxf(f1.y, 0.0f);

        // head partials from this lane's 4 h values
        ull o0 = bo0, o1 = bo1, o2 = bo2, o3 = bo3, o4 = bo4, o5 = bo5;
        {
            ull x = dup2(h0);
            fma2(o0, wq[0][0], x); fma2(o1, wq[0][1], x); fma2(o2, wq[0][2], x);
            fma2(o3, wq[0][3], x); fma2(o4, wq[0][4], x); fma2(o5, wq[0][5], x);
        }
        {
            ull x = dup2(h1);
            fma2(o0, wq[1][0], x); fma2(o1, wq[1][1], x); fma2(o2, wq[1][2], x);
            fma2(o3, wq[1][3], x); fma2(o4, wq[1][4], x); fma2(o5, wq[1][5], x);
        }
        {
            ull x = dup2(h2);
            fma2(o0, wq[2][0], x); fma2(o1, wq[2][1], x); fma2(o2, wq[2][2], x);
            fma2(o3, wq[2][3], x); fma2(o4, wq[2][4], x); fma2(o5, wq[2][5], x);
        }
        {
            ull x = dup2(h3);
            fma2(o0, wq[3][0], x); fma2(o1, wq[3][1], x); fma2(o2, wq[3][2], x);
            fma2(o3, wq[3][3], x); fma2(o4, wq[3][4], x); fma2(o5, wq[3][5], x);
        }

        // 3-round butterfly within the 8-lane group (xor stays in-group)
#pragma unroll
        for (int dlt = 1; dlt <= 4; dlt <<= 1) {
            o0 = add2(o0, __shfl_xor_sync(0xFFFFFFFFu, o0, dlt));
            o1 = add2(o1, __shfl_xor_sync(0xFFFFFFFFu, o1, dlt));
            o2 = add2(o2, __shfl_xor_sync(0xFFFFFFFFu, o2, dlt));
            o3 = add2(o3, __shfl_xor_sync(0xFFFFFFFFu, o3, dlt));
            o4 = add2(o4, __shfl_xor_sync(0xFFFFFFFFu, o4, dlt));
            o5 = add2(o5, __shfl_xor_sync(0xFFFFFFFFu, o5, dlt));
        }

        // split stores: lane r<5 stores digit pair r, lane 5 stores carry
        if (r < 5) {
            ull ov = (r == 0) ? o0 : (r == 1) ? o1 : (r == 2) ? o2 : (r == 3) ? o3 : o4;
            *(float2*)(oDigit + l * 10 + 2 * r) = upk2(ov);
        } else if (r == 5) {
            *(float2*)(oCarry + l * 2) = upk2(o5);
        }

        // next carry prob (identical in all lanes): sigmoid(c0 - c1)
        float2 cv = upk2(o5);
        p0 = 1.0f / (1.0f + expf(cv.y - cv.x));
    }
}

extern "C" void kernel_launch(void* const* d_in, const int* in_sizes, int n_in,
                              void* d_out, int out_size)
{
    const int*   A  = (const int*)  d_in[0];
    const int*   Bd = (const int*)  d_in[1];
    const float* Ea = (const float*)d_in[2];
    const float* Eb = (const float*)d_in[3];
    const float* W1 = (const float*)d_in[4];
    const float* b1 = (const float*)d_in[5];
    const float* W2 = (const float*)d_in[6];
    const float* b2 = (const float*)d_in[7];
    const float* Wd = (const float*)d_in[8];
    const float* bd = (const float*)d_in[9];
    const float* Wc = (const float*)d_in[10];
    const float* bc = (const float*)d_in[11];

    int Bn = in_sizes[0] / 64;
    if (Bn > MAXB) Bn = MAXB;

    digits_kernel<<<(Bn + 63) / 64, 256>>>(A, Bd, Bn);
    precomp_kernel<<<NIDX, 64>>>(Ea, Eb, W1, b1, W2, b2);
    mlp_seq_kernel<<<(Bn * 8 + 127) / 128, 128>>>(Wd, bd, Wc, bc, (float*)d_out, Bn);
}

// round 16
// speedup vs baseline: 5.3667x; 1.1998x over previous
#include <cuda_runtime.h>
#include <math.h>

typedef unsigned long long ull;

#define NIDX 100
#define NSEG 65      // segments 0..64 (<=64 knees), index 64 = 2.0f sentinel
#define MAXB 65536

// ---- persistent scratch (module statics; the sanctioned scratch path) ----
__device__ __align__(16) float gKnees[NIDX * NSEG];        // sorted knees, padded with 2.0f
__device__ __align__(16) float gAB[NIDX * NSEG * 64];      // [idx][seg][0..31]=A, [32..63]=B
__device__ unsigned char gIdxT[64 * MAXB];                 // [l][b] packed digit-pair index

// ---- packed f32x2 helpers ----
__device__ __forceinline__ ull pk2(float x, float y) {
    ull r; asm("mov.b64 %0, {%1, %2};" : "=l"(r) : "f"(x), "f"(y)); return r;
}
__device__ __forceinline__ ull dup2(float x) {
    ull r; asm("mov.b64 %0, {%1, %1};" : "=l"(r) : "f"(x)); return r;
}
__device__ __forceinline__ void fma2(ull& d, ull a, ull b) {
    asm("fma.rn.f32x2 %0, %1, %2, %0;" : "+l"(d) : "l"(a), "l"(b));
}
__device__ __forceinline__ float2 upk2(ull v) {
    float2 r; asm("mov.b64 {%0, %1}, %2;" : "=f"(r.x), "=f"(r.y) : "l"(v)); return r;
}
__device__ __forceinline__ ull add2(ull a, ull b) {
    ull r; asm("add.rn.f32x2 %0, %1, %2;" : "=l"(r) : "l"(a), "l"(b)); return r;
}

// ================= kernel T: pack digits, transpose to [l][b] u8 =================
__global__ void digits_kernel(const int* __restrict__ A, const int* __restrict__ Bd, int Bn)
{
    __shared__ unsigned char tile[64][65];
    int b0 = blockIdx.x * 64;
    for (int t = threadIdx.x; t < 64 * 64; t += 256) {
        int bl = t >> 6, l = t & 63;
        int bi = b0 + bl;
        if (bi < Bn) {
            int av = A[bi * 64 + l], bv = Bd[bi * 64 + l];
            tile[l][bl] = (unsigned char)(av * 10 + bv);
        }
    }
    __syncthreads();
    for (int t = threadIdx.x; t < 64 * 64; t += 256) {
        int l = t >> 6, bl = t & 63;
        if (b0 + bl < Bn)
            gIdxT[l * Bn + b0 + bl] = tile[l][bl];
    }
}

// ================= kernel P: build knees + per-segment (A,B) tables =================
__global__ void precomp_kernel(const float* __restrict__ Ea, const float* __restrict__ Eb,
                               const float* __restrict__ W1, const float* __restrict__ b1,
                               const float* __restrict__ W2, const float* __restrict__ b2)
{
    __shared__ float st[64], sd[64], skey[64], sortedK[64];
    __shared__ int   sortedJ[64];

    const int idx = blockIdx.x;          // 0..99
    const int j   = threadIdx.x;         // 0..63
    const int da = idx / 10, db = idx - 10 * (idx / 10);

    const float* w = W1 + j * 18;
    float t = b1[j] + w[17];
#pragma unroll
    for (int k = 0; k < 8; k++) t = fmaf(Ea[da * 8 + k], w[k], t);
#pragma unroll
    for (int k = 0; k < 8; k++) t = fmaf(Eb[db * 8 + k], w[8 + k], t);
    float d = w[16] - w[17];
    st[j] = t; sd[j] = d;

    float knee = 2.0f;
    if (d != 0.0f) {
        float kn = -t / d;
        if (kn > 0.0f && kn < 1.0f) knee = kn;
    }
    skey[j] = knee;
    __syncthreads();

    int rank = 0;
    for (int m = 0; m < 64; m++) {
        float km = skey[m];
        rank += (km < knee) || (km == knee && m < j);
    }
    sortedK[rank] = knee; sortedJ[rank] = j;
    __syncthreads();

    gKnees[idx * NSEG + j] = sortedK[j];
    if (j == 0) gKnees[idx * NSEG + 64] = 2.0f;

    if (j < 32) {
        const int i = j;
        float Av = b2[i], Bv = 0.0f;
#pragma unroll 1
        for (int m = 0; m < 64; m++) {
            float tm = st[m], dm = sd[m];
            bool act = (tm > 0.0f) || (tm == 0.0f && dm > 0.0f);
            if (act) {
                float wv = W2[i * 64 + m];
                Av = fmaf(wv, tm, Av);
                Bv = fmaf(wv, dm, Bv);
            }
        }
        float* base = gAB + idx * NSEG * 64;
        base[i] = Av; base[32 + i] = Bv;
#pragma unroll 1
        for (int s = 1; s <= 64; s++) {
            float key = sortedK[s - 1];
            if (key < 1.0f) {
                int jj = sortedJ[s - 1];
                float sgn = (sd[jj] > 0.0f) ? 1.0f : -1.0f;
                float wv = W2[i * 64 + jj];
                Av = fmaf(sgn * wv, st[jj], Av);
                Bv = fmaf(sgn * wv, sd[jj], Bv);
            }
            base[s * 64 + i] = Av; base[s * 64 + 32 + i] = Bv;
        }
    }
}

// ---- per-row step compute: h from (A,B,p0), 12-wide head, 8-lane butterfly ----
__device__ __forceinline__ float row_step(
    float4 av, float4 bv, float p0, const ull (*wq)[6], ull bcp, ull obias,
    float* oDigit, float* oCarry, int l, int r)
{
    const ull p0p = dup2(p0);
    ull z0 = pk2(av.x, av.y); fma2(z0, pk2(bv.x, bv.y), p0p);
    ull z1 = pk2(av.z, av.w); fma2(z1, pk2(bv.z, bv.w), p0p);
    float2 f0 = upk2(z0), f1 = upk2(z1);
    float h0 = fmaxf(f0.x, 0.0f), h1 = fmaxf(f0.y, 0.0f);
    float h2 = fmaxf(f1.x, 0.0f), h3 = fmaxf(f1.y, 0.0f);

    ull o0 = 0, o1 = 0, o2 = 0, o3 = 0, o4 = 0, o5 = 0;
    {
        ull x = dup2(h0);
        fma2(o0, wq[0][0], x); fma2(o1, wq[0][1], x); fma2(o2, wq[0][2], x);
        fma2(o3, wq[0][3], x); fma2(o4, wq[0][4], x); fma2(o5, wq[0][5], x);
    }
    {
        ull x = dup2(h1);
        fma2(o0, wq[1][0], x); fma2(o1, wq[1][1], x); fma2(o2, wq[1][2], x);
        fma2(o3, wq[1][3], x); fma2(o4, wq[1][4], x); fma2(o5, wq[1][5], x);
    }
    {
        ull x = dup2(h2);
        fma2(o0, wq[2][0], x); fma2(o1, wq[2][1], x); fma2(o2, wq[2][2], x);
        fma2(o3, wq[2][3], x); fma2(o4, wq[2][4], x); fma2(o5, wq[2][5], x);
    }
    {
        ull x = dup2(h3);
        fma2(o0, wq[3][0], x); fma2(o1, wq[3][1], x); fma2(o2, wq[3][2], x);
        fma2(o3, wq[3][3], x); fma2(o4, wq[3][4], x); fma2(o5, wq[3][5], x);
    }

#pragma unroll
    for (int dlt = 1; dlt <= 4; dlt <<= 1) {
        o0 = add2(o0, __shfl_xor_sync(0xFFFFFFFFu, o0, dlt));
        o1 = add2(o1, __shfl_xor_sync(0xFFFFFFFFu, o1, dlt));
        o2 = add2(o2, __shfl_xor_sync(0xFFFFFFFFu, o2, dlt));
        o3 = add2(o3, __shfl_xor_sync(0xFFFFFFFFu, o3, dlt));
        o4 = add2(o4, __shfl_xor_sync(0xFFFFFFFFu, o4, dlt));
        o5 = add2(o5, __shfl_xor_sync(0xFFFFFFFFu, o5, dlt));
    }

    float2 cv = upk2(add2(o5, bcp));           // carry logits (bias added once, post-reduction)

    if (r < 5) {
        ull ov = (r == 0) ? o0 : (r == 1) ? o1 : (r == 2) ? o2 : (r == 3) ? o3 : o4;
        *(float2*)(oDigit + l * 10 + 2 * r) = upk2(add2(ov, obias));
    } else if (r == 5) {
        *(float2*)(oCarry + l * 2) = cv;
    }

    return __fdividef(1.0f, 1.0f + __expf(cv.y - cv.x));
}

// ================= kernel M: 8 lanes = 1 row, 2 rows per group (ILP) =================
__global__ __launch_bounds__(128, 3)
void mlp_seq_kernel(const float* __restrict__ Wd, const float* __restrict__ bd,
                    const float* __restrict__ Wc, const float* __restrict__ bc,
                    float* __restrict__ out, int Bn)
{
    __shared__ float sKnees[NIDX * NSEG];                 // 26 KB

    const int tid = threadIdx.x;
    for (int t = tid; t < NIDX * NSEG; t += 128)
        sKnees[t] = gKnees[t];
    __syncthreads();

    const int lane = tid & 31;
    const int r    = lane & 7;                            // lane-in-group
    const int grp  = lane >> 3;                           // group-in-warp (ballot byte)
    const int gid  = tid >> 3;                            // group-in-block 0..15

    int bi0 = blockIdx.x * 32 + 2 * gid;                  // 32 rows per block
    int bi1 = bi0 + 1;
    if (bi0 >= Bn) bi0 = Bn - 1;                          // duplicate tail rows
    if (bi1 >= Bn) bi1 = Bn - 1;

    // register-resident head weights for this lane's 4 h-indices
    ull wq[4][6];
#pragma unroll
    for (int m = 0; m < 4; m++) {
        int i = 4 * r + m;
#pragma unroll
        for (int k2 = 0; k2 < 6; k2++) {
            int k0 = 2 * k2, k1 = k0 + 1;
            float w0 = (k0 < 10) ? Wd[k0 * 32 + i] : Wc[(k0 - 10) * 32 + i];
            float w1 = (k1 < 10) ? Wd[k1 * 32 + i] : Wc[(k1 - 10) * 32 + i];
            wq[m][k2] = pk2(w0, w1);
        }
    }
    const ull bcp   = pk2(bc[0], bc[1]);                         // carry bias (all lanes)
    const ull obias = (r < 5) ? pk2(bd[2 * r], bd[2 * r + 1]) : 0ull;

    float* oD0 = out + (ull)bi0 * 640;
    float* oD1 = out + (ull)bi1 * 640;
    float* oC0 = out + (ull)Bn * 640 + (ull)bi0 * 128;
    float* oC1 = out + (ull)Bn * 640 + (ull)bi1 * 128;

    float p0a = 1.0f, p0b = 1.0f;                         // carry0 = (1,0)

#pragma unroll 1
    for (int l = 0; l < 64; l++) {
        const int ia = (int)gIdxT[l * Bn + bi0];
        const int ib = (int)gIdxT[l * Bn + bi1];

        // ---- warp-parallel binary search (2 ballot rounds per row) ----
        const float* kna = sKnees + ia * NSEG;
        const float* knb = sKnees + ib * NSEG;
        unsigned ma = __ballot_sync(0xFFFFFFFFu, kna[8 * r + 7] < p0a);
        unsigned mb = __ballot_sync(0xFFFFFFFFu, knb[8 * r + 7] < p0b);
        int loa = 8 * __popc((ma >> (grp * 8)) & 0xFF);
        int lob = 8 * __popc((mb >> (grp * 8)) & 0xFF);
        ma = __ballot_sync(0xFFFFFFFFu, kna[min(loa + r, 64)] < p0a);
        mb = __ballot_sync(0xFFFFFFFFu, knb[min(lob + r, 64)] < p0b);
        loa += __popc((ma >> (grp * 8)) & 0xFF);
        lob += __popc((mb >> (grp * 8)) & 0xFF);

        // ---- both rows' AB fetches in flight before either compute ----
        const float* basea = gAB + (ia * NSEG + loa) * 64;
        const float* baseb = gAB + (ib * NSEG + lob) * 64;
        float4 ava = *(const float4*)(basea + 4 * r);
        float4 bva = *(const float4*)(basea + 32 + 4 * r);
        float4 avb = *(const float4*)(baseb + 4 * r);
        float4 bvb = *(const float4*)(baseb + 32 + 4 * r);

        // row 0 compute hides row 1's load latency
        p0a = row_step(ava, bva, p0a, wq, bcp, obias, oD0, oC0, l, r);
        p0b = row_step(avb, bvb, p0b, wq, bcp, obias, oD1, oC1, l, r);
    }
}

extern "C" void kernel_launch(void* const* d_in, const int* in_sizes, int n_in,
                              void* d_out, int out_size)
{
    const int*   A  = (const int*)  d_in[0];
    const int*   Bd = (const int*)  d_in[1];
    const float* Ea = (const float*)d_in[2];
    const float* Eb = (const float*)d_in[3];
    const float* W1 = (const float*)d_in[4];
    const float* b1 = (const float*)d_in[5];
    const float* W2 = (const float*)d_in[6];
    const float* b2 = (const float*)d_in[7];
    const float* Wd = (const float*)d_in[8];
    const float* bd = (const float*)d_in[9];
    const float* Wc = (const float*)d_in[10];
    const float* bc = (const float*)d_in[11];

    int Bn = in_sizes[0] / 64;
    if (Bn > MAXB) Bn = MAXB;

    digits_kernel<<<(Bn + 63) / 64, 256>>>(A, Bd, Bn);
    precomp_kernel<<<NIDX, 64>>>(Ea, Eb, W1, b1, W2, b2);
    mlp_seq_kernel<<<(Bn + 31) / 32, 128>>>(Wd, bd, Wc, bc, (float*)d_out, Bn);
}